// round 10
// baseline (speedup 1.0000x reference)
#include <cuda_runtime.h>
#include <cstdint>
#include <cstddef>

// ---------------------------------------------------------------------------
// Problem constants
// ---------------------------------------------------------------------------
#define BSZ       8
#define SEQ       1024
#define DIM       1024
#define NHEAD     16
#define HDIM      64
#define MTOT      (BSZ * SEQ)        // 8192
#define CATD      (DIM + HDIM)       // 1088
#define FFD       (2 * DIM)          // 2048
#define L2E       1.4426950408889634f

// ---------------------------------------------------------------------------
// Scratch (static device globals; no allocation anywhere)
// ---------------------------------------------------------------------------
__device__ float g_CAT[(size_t)MTOT * CATD];
__device__ float g_H1[(size_t)MTOT * FFD];

// Fragment-major tf32 Q/K/V per (b,h): 65536 u32 each, 128 bh slots.
//  Q: [qt 64][ks 8][lane 32][reg 4]   (m16n8k8 A-fragments, rows=query, k=d)
//  K: [nt 128][ks 8][lane 32][reg 2]  (B-frags for S=Q.K^T, keys column-permuted)
//  V: [kk 128][dt 8][lane 32][reg 2]  (B-frags for O=P.V, natural key order)
__device__ uint32_t g_QF[(size_t)128 * 65536];
__device__ uint32_t g_KF[(size_t)128 * 65536];
__device__ uint32_t g_VF[(size_t)128 * 65536];

// Pre-permuted tf32 weights (fragment-major B operands, 256-wide N panels).
#define WP_Q   0
#define WP_K   1048576
#define WP_V   2097152
#define WP_IN  3145728          // Win padded to Npad=256 -> 262144
#define WP_1   3407872
#define WP_2   5636096
#define WP_TOT 7733248
__device__ uint32_t g_WP[WP_TOT];

// ---------------------------------------------------------------------------
// helpers
// ---------------------------------------------------------------------------
__device__ __forceinline__ uint32_t smem_u32(const void* p) {
    uint32_t a;
    asm("{ .reg .u64 t; cvta.to.shared.u64 t, %1; cvt.u32.u64 %0, t; }"
        : "=r"(a) : "l"(p));
    return a;
}
__device__ __forceinline__ uint32_t f32_tf32(float f) {
    uint32_t u;
    asm("cvt.rna.tf32.f32 %0, %1;" : "=r"(u) : "f"(f));
    return u;
}
__device__ __forceinline__ void mma_tf32(float* c, uint4 a, uint32_t b0, uint32_t b1) {
    asm volatile(
        "mma.sync.aligned.m16n8k8.row.col.f32.tf32.tf32.f32 "
        "{%0,%1,%2,%3}, {%4,%5,%6,%7}, {%8,%9}, {%0,%1,%2,%3};"
        : "+f"(c[0]), "+f"(c[1]), "+f"(c[2]), "+f"(c[3])
        : "r"(a.x), "r"(a.y), "r"(a.z), "r"(a.w), "r"(b0), "r"(b1));
}

// ---------------------------------------------------------------------------
// Weight permutation: W[k][n] -> fragment-major tf32 B operand.
// 256-wide N panels: dest[nblk][kblk 32k][nt*4+kt][lane][reg]
//   nblk = n>>8, nt = (n>>3)&31.  Zero-fill n >= Nn.
// ---------------------------------------------------------------------------
__global__ void permute_w(const float* __restrict__ W, uint32_t* __restrict__ Wp,
                          int K, int Nn, int Npad)
{
    const int idx = blockIdx.x * 256 + threadIdx.x;
    const int rowlen4 = Npad >> 2;
    const int k = idx / rowlen4;
    if (k >= K) return;
    const int n4 = (idx - k * rowlen4) << 2;

    float4 v = make_float4(0.f, 0.f, 0.f, 0.f);
    if (n4 < Nn) v = *(const float4*)(W + (size_t)k * Nn + n4);

    const int nblk = n4 >> 8;
    const int nt   = (n4 >> 3) & 31;
    const int nnb  = n4 & 7;
    const int kblk = k >> 5;
    const int kt   = (k >> 3) & 3;
    const int kk   = k & 7;
    const int reg  = kk >> 2;
    const int kk3  = kk & 3;

    uint32_t* d = Wp + (size_t)nblk * K * 256 + (size_t)kblk * 8192
                     + (size_t)(nt * 4 + kt) * 64 + reg;
    d[((nnb + 0) * 4 + kk3) * 2] = f32_tf32(v.x);
    d[((nnb + 1) * 4 + kk3) * 2] = f32_tf32(v.y);
    d[((nnb + 2) * 4 + kk3) * 2] = f32_tf32(v.z);
    d[((nnb + 3) * 4 + kk3) * 2] = f32_tf32(v.w);
}

// ---------------------------------------------------------------------------
// tf32 mma.sync GEMM: C = op(A[M,K] @ W[K,N] + bias)
//   128x256 block tile, BK=32, 8 warps (2x4), 64x64 warp tiles, m16n8k8.
//   mode 0: standard float store  mode 1/2/3: Q/K/V fragment scatter (tf32)
// ---------------------------------------------------------------------------
#define BM 128
#define BN 256
#define A_FSTRIDE   132
#define A_STAGE_U32 (32 * A_FSTRIDE)          // 4224
#define B_STAGE_U32 8192
#define STAGE_U32   (A_STAGE_U32 + B_STAGE_U32)   // 12416
#define GEMM_SMEM   (2 * STAGE_U32 * 4)       // 99328 bytes

__global__ __launch_bounds__(256, 1) void mma_gemm(
    const float* __restrict__ A, const uint32_t* __restrict__ Bp,
    const float* __restrict__ bias, void* __restrict__ Cv,
    int Nn, int K, int ldc, int col_off,
    float scale, int do_relu, int mode)
{
    extern __shared__ uint32_t S[];
    const uint32_t sbase = smem_u32(S);
    const int tid  = threadIdx.x;
    const int lane = tid & 31;
    const int wid  = tid >> 5;
    const int g    = lane >> 2;
    const int tig  = lane & 3;
    const int wm   = wid >> 2;   // 0..1  (64 rows each)
    const int wn   = wid & 3;    // 0..3  (64 cols each)
    const int bm   = blockIdx.y * BM;
    const int bn   = blockIdx.x * BN;
    const int T    = K >> 5;

    const int arow = tid >> 3;
    const int ac4  = (tid & 7) << 2;
    const int a_kt   = ac4 >> 3;
    const int a_kkb  = ac4 & 7;
    const int a_regb = ((arow >> 3) & 1) + ((a_kkb >> 2) << 1);
    const int a_lb   = (arow & 7) << 2;

    const float*    Ag = A + (size_t)bm * K;
    const uint32_t* Bg = Bp + (size_t)blockIdx.x * K * 256;

    float acc[4][8][4];
#pragma unroll
    for (int i = 0; i < 4; i++)
#pragma unroll
        for (int j = 0; j < 8; j++)
#pragma unroll
            for (int r = 0; r < 4; r++) acc[i][j][r] = 0.f;

    float4 areg[4];

    auto LDG_A = [&](int t) {
#pragma unroll
        for (int i = 0; i < 4; i++) {
            const int row = arow + i * 32;
            areg[i] = *(const float4*)(Ag + (size_t)row * K + t * 32 + ac4);
        }
    };
    auto STS_A = [&](int s) {
        uint32_t* As = S + s * STAGE_U32;
#pragma unroll
        for (int i = 0; i < 4; i++) {
            const int mt = (arow + i * 32) >> 4;
            uint32_t* p = As + (mt * 4 + a_kt) * A_FSTRIDE + a_regb;
            p[(a_lb + 0) * 4] = f32_tf32(areg[i].x);
            p[(a_lb + 1) * 4] = f32_tf32(areg[i].y);
            p[(a_lb + 2) * 4] = f32_tf32(areg[i].z);
            p[(a_lb + 3) * 4] = f32_tf32(areg[i].w);
        }
    };
    auto CPA_B = [&](int t, int s) {
        const uint32_t dstb = sbase + (s * STAGE_U32 + A_STAGE_U32) * 4;
        const uint32_t* src = Bg + (size_t)t * 8192 + tid * 4;
#pragma unroll
        for (int i = 0; i < 8; i++) {
            asm volatile("cp.async.cg.shared.global [%0], [%1], 16;"
                         :: "r"(dstb + (uint32_t)(tid + i * 256) * 16),
                            "l"(src + i * 1024) : "memory");
        }
    };
    auto COMPUTE = [&](int s) {
        const uint32_t* As = S + s * STAGE_U32;
        const uint32_t* Bs = As + A_STAGE_U32;
#pragma unroll
        for (int kt = 0; kt < 4; kt++) {
            uint4 af[4];
            uint2 bf[8];
#pragma unroll
            for (int mi = 0; mi < 4; mi++)
                af[mi] = *(const uint4*)(As + ((wm * 4 + mi) * 4 + kt) * A_FSTRIDE
                                            + lane * 4);
#pragma unroll
            for (int ni = 0; ni < 8; ni++)
                bf[ni] = *(const uint2*)(Bs + ((wn * 8 + ni) * 4 + kt) * 64
                                            + lane * 2);
#pragma unroll
            for (int mi = 0; mi < 4; mi++)
#pragma unroll
                for (int ni = 0; ni < 8; ni++)
                    mma_tf32(acc[mi][ni], af[mi], bf[ni].x, bf[ni].y);
        }
    };

    CPA_B(0, 0);
    asm volatile("cp.async.commit_group;" ::: "memory");
    LDG_A(0);
    STS_A(0);

    for (int t = 0; t < T; t++) {
        const int s = t & 1;
        if (t + 1 < T) {
            CPA_B(t + 1, s ^ 1);
            asm volatile("cp.async.commit_group;" ::: "memory");
            LDG_A(t + 1);
            asm volatile("cp.async.wait_group 1;" ::: "memory");
        } else {
            asm volatile("cp.async.wait_group 0;" ::: "memory");
        }
        __syncthreads();
        COMPUTE(s);
        if (t + 1 < T) STS_A(s ^ 1);
        __syncthreads();
    }

    if (mode == 0) {
        float* C = (float*)Cv;
#pragma unroll
        for (int mi = 0; mi < 4; mi++) {
            const int r0 = bm + (wm * 4 + mi) * 16 + g;
#pragma unroll
            for (int ni = 0; ni < 8; ni++) {
                const int c = bn + (wn * 8 + ni) * 8 + tig * 2;
                if (c < Nn) {
                    const float2 bv = *(const float2*)(bias + c);
                    float2 v0, v1;
                    v0.x = (acc[mi][ni][0] + bv.x) * scale;
                    v0.y = (acc[mi][ni][1] + bv.y) * scale;
                    v1.x = (acc[mi][ni][2] + bv.x) * scale;
                    v1.y = (acc[mi][ni][3] + bv.y) * scale;
                    if (do_relu) {
                        v0.x = fmaxf(v0.x, 0.f); v0.y = fmaxf(v0.y, 0.f);
                        v1.x = fmaxf(v1.x, 0.f); v1.y = fmaxf(v1.y, 0.f);
                    }
                    *(float2*)(C + (size_t)r0 * ldc + col_off + c) = v0;
                    *(float2*)(C + (size_t)(r0 + 8) * ldc + col_off + c) = v1;
                }
            }
        }
    } else {
        uint32_t* Cu = (uint32_t*)Cv;
        auto store_frag = [&](int r, int cc, float v) {
            const int b = r >> 10, seq = r & 1023;
            const int h = cc >> 6, d = cc & 63;
            const uint32_t base = (uint32_t)(b * 16 + h) * 65536u;
            uint32_t addr;
            if (mode == 1) {          // Q: A-frag
                addr = base + (uint32_t)((seq >> 4) * 8 + (d >> 3)) * 128u
                     + (uint32_t)((seq & 7) * 4 + (d & 3)) * 4u
                     + (uint32_t)(((seq >> 3) & 1) + 2 * ((d >> 2) & 1));
            } else if (mode == 2) {   // K: B-frag, permuted key columns
                const uint32_t j = (uint32_t)(((seq & 3) << 1) | ((seq >> 2) & 1));
                addr = base + (uint32_t)((seq >> 3) * 8 + (d >> 3)) * 64u
                     + (j * 4 + (uint32_t)(d & 3)) * 2u + (uint32_t)((d >> 2) & 1);
            } else {                  // V: B-frag, natural order
                addr = base + (uint32_t)((seq >> 3) * 8 + (d >> 3)) * 64u
                     + (uint32_t)((d & 7) * 4 + (seq & 3)) * 2u
                     + (uint32_t)((seq >> 2) & 1);
            }
            Cu[addr] = f32_tf32(v);
        };
#pragma unroll
        for (int mi = 0; mi < 4; mi++) {
            const int r0 = bm + (wm * 4 + mi) * 16 + g;
#pragma unroll
            for (int ni = 0; ni < 8; ni++) {
                const int c = bn + (wn * 8 + ni) * 8 + tig * 2;
                const float2 bv = *(const float2*)(bias + c);
                store_frag(r0,     c,     (acc[mi][ni][0] + bv.x) * scale);
                store_frag(r0,     c + 1, (acc[mi][ni][1] + bv.y) * scale);
                store_frag(r0 + 8, c,     (acc[mi][ni][2] + bv.x) * scale);
                store_frag(r0 + 8, c + 1, (acc[mi][ni][3] + bv.y) * scale);
            }
        }
    }
}

// ---------------------------------------------------------------------------
// Flash attention via tf32 mma.sync (unchanged from R8, passing).
// ---------------------------------------------------------------------------
#define ATT_SMEM (2 * 16384 * 4)      // 131072 B

__global__ __launch_bounds__(256, 1) void attn_mma(
    const uint32_t* __restrict__ Qf, const uint32_t* __restrict__ Kf,
    const uint32_t* __restrict__ Vf, float* __restrict__ OUT)
{
    extern __shared__ uint32_t S[];   // [2][K 8192 | V 8192]
    const uint32_t sbase = smem_u32(S);
    const int tid  = threadIdx.x;
    const int lane = tid & 31;
    const int w    = tid >> 5;
    const int g    = lane >> 2;
    const int tig  = lane & 3;
    const int qb   = blockIdx.x;
    const int bh   = blockIdx.y;

    const uint32_t* Qb = Qf + (size_t)bh * 65536;
    const uint32_t* Kb = Kf + (size_t)bh * 65536;
    const uint32_t* Vb = Vf + (size_t)bh * 65536;

    uint4 qf[8];
    {
        const uint32_t* qp = Qb + (size_t)((qb * 8 + w) * 8) * 128 + lane * 4;
#pragma unroll
        for (int ks = 0; ks < 8; ks++)
            qf[ks] = *(const uint4*)(qp + ks * 128);
    }

    float o[8][4];
#pragma unroll
    for (int dt = 0; dt < 8; dt++)
#pragma unroll
        for (int r = 0; r < 4; r++) o[dt][r] = 0.f;
    float m0 = -1e30f, m1 = -1e30f, l0 = 0.f, l1 = 0.f;

    auto CPA = [&](int t, int s) {
        const uint32_t kd = sbase + (uint32_t)(s * 16384) * 4 + tid * 16;
        const uint32_t vd = kd + 8192 * 4;
        const uint32_t* ks_ = Kb + (size_t)t * 8192 + tid * 4;
        const uint32_t* vs_ = Vb + (size_t)t * 8192 + tid * 4;
#pragma unroll
        for (int i = 0; i < 8; i++) {
            asm volatile("cp.async.cg.shared.global [%0], [%1], 16;"
                         :: "r"(kd + i * 4096u), "l"(ks_ + i * 1024) : "memory");
            asm volatile("cp.async.cg.shared.global [%0], [%1], 16;"
                         :: "r"(vd + i * 4096u), "l"(vs_ + i * 1024) : "memory");
        }
    };

    CPA(0, 0);
    asm volatile("cp.async.commit_group;" ::: "memory");

    for (int t = 0; t < 8; t++) {
        const int s = t & 1;
        asm volatile("cp.async.wait_group 0;" ::: "memory");
        __syncthreads();
        if (t + 1 < 8) {
            CPA(t + 1, s ^ 1);
            asm volatile("cp.async.commit_group;" ::: "memory");
        }
        const uint32_t* Ksm = S + s * 16384;
        const uint32_t* Vsm = Ksm + 8192;

        float sc[16][4];
#pragma unroll
        for (int nt = 0; nt < 16; nt++) {
            sc[nt][0] = 0.f; sc[nt][1] = 0.f; sc[nt][2] = 0.f; sc[nt][3] = 0.f;
#pragma unroll
            for (int ks = 0; ks < 8; ks++) {
                const uint2 b = *(const uint2*)(Ksm + (nt * 8 + ks) * 64 + lane * 2);
                mma_tf32(sc[nt], qf[ks], b.x, b.y);
            }
        }

        if (t == qb) {
            const int q0 = w * 16 + g;
#pragma unroll
            for (int nt = 0; nt < 16; nt++) {
                const int k0 = nt * 8 + tig;
                if (k0     == q0)     sc[nt][0] = -1e30f;
                if (k0 + 4 == q0)     sc[nt][1] = -1e30f;
                if (k0     == q0 + 8) sc[nt][2] = -1e30f;
                if (k0 + 4 == q0 + 8) sc[nt][3] = -1e30f;
            }
        }

        float mt0 = -1e30f, mt1 = -1e30f;
#pragma unroll
        for (int nt = 0; nt < 16; nt++) {
            mt0 = fmaxf(mt0, fmaxf(sc[nt][0], sc[nt][1]));
            mt1 = fmaxf(mt1, fmaxf(sc[nt][2], sc[nt][3]));
        }
        mt0 = fmaxf(mt0, __shfl_xor_sync(0xFFFFFFFFu, mt0, 1));
        mt0 = fmaxf(mt0, __shfl_xor_sync(0xFFFFFFFFu, mt0, 2));
        mt1 = fmaxf(mt1, __shfl_xor_sync(0xFFFFFFFFu, mt1, 1));
        mt1 = fmaxf(mt1, __shfl_xor_sync(0xFFFFFFFFu, mt1, 2));
        const float nm0 = fmaxf(m0, mt0), nm1 = fmaxf(m1, mt1);
        const float cr0 = exp2f((m0 - nm0) * L2E);
        const float cr1 = exp2f((m1 - nm1) * L2E);
        m0 = nm0; m1 = nm1;
        l0 *= cr0; l1 *= cr1;
#pragma unroll
        for (int dt = 0; dt < 8; dt++) {
            o[dt][0] *= cr0; o[dt][1] *= cr0;
            o[dt][2] *= cr1; o[dt][3] *= cr1;
        }
        const float b0 = nm0 * L2E, b1 = nm1 * L2E;
#pragma unroll
        for (int nt = 0; nt < 16; nt++) {
            const float p0 = exp2f(fmaf(sc[nt][0], L2E, -b0));
            const float p1 = exp2f(fmaf(sc[nt][1], L2E, -b0));
            const float p2 = exp2f(fmaf(sc[nt][2], L2E, -b1));
            const float p3 = exp2f(fmaf(sc[nt][3], L2E, -b1));
            l0 += p0 + p1; l1 += p2 + p3;
            sc[nt][0] = __uint_as_float(f32_tf32(p0));
            sc[nt][1] = __uint_as_float(f32_tf32(p2));
            sc[nt][2] = __uint_as_float(f32_tf32(p1));
            sc[nt][3] = __uint_as_float(f32_tf32(p3));
        }

#pragma unroll
        for (int kk = 0; kk < 16; kk++) {
            const uint4 a = make_uint4(__float_as_uint(sc[kk][0]),
                                       __float_as_uint(sc[kk][1]),
                                       __float_as_uint(sc[kk][2]),
                                       __float_as_uint(sc[kk][3]));
#pragma unroll
            for (int dt = 0; dt < 8; dt++) {
                const uint2 b = *(const uint2*)(Vsm + (kk * 8 + dt) * 64 + lane * 2);
                mma_tf32(o[dt], a, b.x, b.y);
            }
        }
    }

    l0 += __shfl_xor_sync(0xFFFFFFFFu, l0, 1);
    l0 += __shfl_xor_sync(0xFFFFFFFFu, l0, 2);
    l1 += __shfl_xor_sync(0xFFFFFFFFu, l1, 1);
    l1 += __shfl_xor_sync(0xFFFFFFFFu, l1, 2);
    const float inv0 = 1.f / l0, inv1 = 1.f / l1;

    const int b_ = bh >> 4, h = bh & 15;
    const int q0 = qb * 128 + w * 16 + g;
    float* base0 = OUT + ((size_t)(b_ * 1024 + q0)) * CATD + h * 64 + tig * 2;
    float* base1 = base0 + (size_t)8 * CATD;
#pragma unroll
    for (int dt = 0; dt < 8; dt++) {
        float2 v0, v1;
        v0.x = o[dt][0] * inv0; v0.y = o[dt][1] * inv0;
        v1.x = o[dt][2] * inv1; v1.y = o[dt][3] * inv1;
        *(float2*)(base0 + dt * 8) = v0;
        *(float2*)(base1 + dt * 8) = v1;
    }
}

// ---------------------------------------------------------------------------
// launch
// ---------------------------------------------------------------------------
extern "C" void kernel_launch(void* const* d_in, const int* in_sizes, int n_in,
                              void* d_out, int out_size)
{
    const float* x    = (const float*)d_in[0];
    const float* Wq   = (const float*)d_in[1];
    const float* bq   = (const float*)d_in[2];
    const float* Wk   = (const float*)d_in[3];
    const float* bk   = (const float*)d_in[4];
    const float* Wv   = (const float*)d_in[5];
    const float* bv   = (const float*)d_in[6];
    const float* Win  = (const float*)d_in[7];
    const float* bin_ = (const float*)d_in[8];
    const float* W1   = (const float*)d_in[9];
    const float* b1   = (const float*)d_in[10];
    const float* W2   = (const float*)d_in[11];
    const float* b2   = (const float*)d_in[12];
    float* out = (float*)d_out;

    float *cat, *h1;
    uint32_t *wp, *qf, *kf, *vf;
    cudaGetSymbolAddress((void**)&cat, g_CAT);
    cudaGetSymbolAddress((void**)&h1,  g_H1);
    cudaGetSymbolAddress((void**)&wp,  g_WP);
    cudaGetSymbolAddress((void**)&qf,  g_QF);
    cudaGetSymbolAddress((void**)&kf,  g_KF);
    cudaGetSymbolAddress((void**)&vf,  g_VF);

    cudaFuncSetAttribute(mma_gemm, cudaFuncAttributeMaxDynamicSharedMemorySize,
                         GEMM_SMEM);
    cudaFuncSetAttribute(attn_mma, cudaFuncAttributeMaxDynamicSharedMemorySize,
                         ATT_SMEM);

    // ---- weight permutation (fragment-major tf32, 256-wide N panels) ----
    permute_w<<<(1024 * 1024 / 4) / 256, 256>>>(Wq,  wp + WP_Q,  1024, 1024, 1024);
    permute_w<<<(1024 * 1024 / 4) / 256, 256>>>(Wk,  wp + WP_K,  1024, 1024, 1024);
    permute_w<<<(1024 * 1024 / 4) / 256, 256>>>(Wv,  wp + WP_V,  1024, 1024, 1024);
    permute_w<<<(1024 * 256  / 4) / 256, 256>>>(Win, wp + WP_IN, 1024, 64,   256);
    permute_w<<<(1088 * 2048 / 4) / 256, 256>>>(W1,  wp + WP_1,  1088, 2048, 2048);
    permute_w<<<(2048 * 1024 / 4) / 256, 256>>>(W2,  wp + WP_2,  2048, 1024, 1024);

    const float scaling = 0.125f;   // HEAD_DIM^-0.5
    dim3 blk(256);

    // Q/K/V projections -> fragment-major tf32 scratch (Q pre-scaled)
    dim3 g_qkv(DIM / BN, MTOT / BM);          // (4, 64)
    mma_gemm<<<g_qkv, blk, GEMM_SMEM>>>(x, wp + WP_Q, bq, qf, DIM, DIM, 0, 0, scaling, 0, 1);
    mma_gemm<<<g_qkv, blk, GEMM_SMEM>>>(x, wp + WP_K, bk, kf, DIM, DIM, 0, 0, 1.0f, 0, 2);
    mma_gemm<<<g_qkv, blk, GEMM_SMEM>>>(x, wp + WP_V, bv, vf, DIM, DIM, 0, 0, 1.0f, 0, 3);

    // in_ projection -> CAT columns [1024, 1088)
    dim3 g_in(1, MTOT / BM);                  // (1, 64)
    mma_gemm<<<g_in, blk, GEMM_SMEM>>>(x, wp + WP_IN, bin_, cat, HDIM, DIM, CATD, DIM, 1.0f, 0, 0);

    // flash attention (tensor cores) -> CAT columns [0, 1024)
    dim3 g_att(8, BSZ * NHEAD);               // (8, 128)
    attn_mma<<<g_att, blk, ATT_SMEM>>>(qf, kf, vf, cat);

    // FFN
    dim3 g_f1(FFD / BN, MTOT / BM);           // (8, 64)
    mma_gemm<<<g_f1, blk, GEMM_SMEM>>>(cat, wp + WP_1, b1, h1, FFD, CATD, FFD, 0, 1.0f, 1, 0);
    dim3 g_f2(DIM / BN, MTOT / BM);           // (4, 64)
    mma_gemm<<<g_f2, blk, GEMM_SMEM>>>(h1, wp + WP_2, b2, out, DIM, FFD, DIM, 0, 1.0f, 0, 0);
}

// round 15
// speedup vs baseline: 1.1127x; 1.1127x over previous
#include <cuda_runtime.h>
#include <cstdint>
#include <cstddef>

// ---------------------------------------------------------------------------
// Problem constants
// ---------------------------------------------------------------------------
#define BSZ       8
#define SEQ       1024
#define DIM       1024
#define NHEAD     16
#define HDIM      64
#define MTOT      (BSZ * SEQ)        // 8192
#define CATD      (DIM + HDIM)       // 1088
#define FFD       (2 * DIM)          // 2048
#define L2E       1.4426950408889634f

// ---------------------------------------------------------------------------
// Scratch (static device globals; no allocation anywhere)
// ---------------------------------------------------------------------------
// A-fragment-major tf32 activations:
//   addr(r,k,Kd) = ((r>>4)*(Kd>>3)+(k>>3))*128 + ((r&7)*4+(k&3))*4
//                + ((r>>3)&1) + 2*((k>>2)&1)
__device__ uint32_t g_XF [(size_t)MTOT * DIM];    // x        (Kd=1024)
__device__ uint32_t g_CATF[(size_t)MTOT * CATD];  // attn|in_ (Kd=1088)
__device__ uint32_t g_H1F[(size_t)MTOT * FFD];    // ffn1 out (Kd=2048)

// Fragment-major tf32 Q/K/V per (b,h): 65536 u32 each, 128 bh slots.
__device__ uint32_t g_QF[(size_t)128 * 65536];
__device__ uint32_t g_KF[(size_t)128 * 65536];
__device__ uint32_t g_VF[(size_t)128 * 65536];

// Pre-permuted tf32 weights (fragment-major B operands, 128-wide N panels).
#define WP_Q   0
#define WP_K   1048576
#define WP_V   2097152
#define WP_IN  3145728
#define WP_1   3276800
#define WP_2   5505024
#define WP_TOT 7602176
__device__ uint32_t g_WP[WP_TOT];

// ---------------------------------------------------------------------------
// helpers
// ---------------------------------------------------------------------------
__device__ __forceinline__ uint32_t smem_u32(const void* p) {
    uint32_t a;
    asm("{ .reg .u64 t; cvta.to.shared.u64 t, %1; cvt.u32.u64 %0, t; }"
        : "=r"(a) : "l"(p));
    return a;
}
__device__ __forceinline__ uint32_t f32_tf32(float f) {
    uint32_t u;
    asm("cvt.rna.tf32.f32 %0, %1;" : "=r"(u) : "f"(f));
    return u;
}
__device__ __forceinline__ void mma_tf32(float* c, uint4 a, uint32_t b0, uint32_t b1) {
    asm volatile(
        "mma.sync.aligned.m16n8k8.row.col.f32.tf32.tf32.f32 "
        "{%0,%1,%2,%3}, {%4,%5,%6,%7}, {%8,%9}, {%0,%1,%2,%3};"
        : "+f"(c[0]), "+f"(c[1]), "+f"(c[2]), "+f"(c[3])
        : "r"(a.x), "r"(a.y), "r"(a.z), "r"(a.w), "r"(b0), "r"(b1));
}
__device__ __forceinline__ uint32_t afrag_addr(int r, int k, int Kd) {
    return (uint32_t)(((r >> 4) * (Kd >> 3) + (k >> 3)) * 128
                    + ((r & 7) * 4 + (k & 3)) * 4
                    + ((r >> 3) & 1) + 2 * ((k >> 2) & 1));
}

// ---------------------------------------------------------------------------
// x -> A-fragment-major tf32
// ---------------------------------------------------------------------------
__global__ void permute_x(const float* __restrict__ X, uint32_t* __restrict__ Xf,
                          int Kd)
{
    const int idx = blockIdx.x * 256 + threadIdx.x;   // float4 id
    const int r  = idx / (Kd >> 2);
    const int k4 = (idx - r * (Kd >> 2)) << 2;
    const float4 v = *(const float4*)(X + (size_t)r * Kd + k4);
    uint32_t* d = Xf + afrag_addr(r, k4, Kd);
    d[0]  = f32_tf32(v.x);
    d[4]  = f32_tf32(v.y);
    d[8]  = f32_tf32(v.z);
    d[12] = f32_tf32(v.w);
}

// ---------------------------------------------------------------------------
// Weight permutation: W[k][n] -> fragment-major tf32 B operand (128-wide panels)
// ---------------------------------------------------------------------------
__global__ void permute_w(const float* __restrict__ W, uint32_t* __restrict__ Wp,
                          int K, int Nn, int Npad)
{
    const int idx = blockIdx.x * 256 + threadIdx.x;
    const int rowlen4 = Npad >> 2;
    const int k = idx / rowlen4;
    if (k >= K) return;
    const int n4 = (idx - k * rowlen4) << 2;

    float4 v = make_float4(0.f, 0.f, 0.f, 0.f);
    if (n4 < Nn) v = *(const float4*)(W + (size_t)k * Nn + n4);

    const int nblk = n4 >> 7;
    const int nt   = (n4 >> 3) & 15;
    const int nnb  = n4 & 7;
    const int kblk = k >> 5;
    const int kt   = (k >> 3) & 3;
    const int kk   = k & 7;
    const int reg  = kk >> 2;
    const int kk3  = kk & 3;

    uint32_t* d = Wp + (size_t)nblk * K * 128 + (size_t)kblk * 4096
                     + (size_t)(nt * 4 + kt) * 64 + reg;
    d[((nnb + 0) * 4 + kk3) * 2] = f32_tf32(v.x);
    d[((nnb + 1) * 4 + kk3) * 2] = f32_tf32(v.y);
    d[((nnb + 2) * 4 + kk3) * 2] = f32_tf32(v.z);
    d[((nnb + 3) * 4 + kk3) * 2] = f32_tf32(v.w);
}

// ---------------------------------------------------------------------------
// tf32 mma.sync GEMM, both operands pre-fragmented in gmem.
//   128x128 block, BK=32, 8 warps (2x4), 64x32 warp tiles, 3-stage cp.async.
//   Pipeline: COMPUTE(s) -> CPA(t+2) -> commit -> wait_group 1 -> barrier
//   (wait BEFORE barrier: cp.async completion is per-thread; the barrier
//    publishes it. R12 had these swapped -> race.)
//   mode 0: float store   1: A-frag store (width Kdst, col_off)
//   2/3/4: Q/K/V scatter
// ---------------------------------------------------------------------------
#define BM 128
#define BN 128
#define A_STAGE_U32 4096
#define B_STAGE_U32 4096
#define STAGE_U32   8192
#define GEMM_SMEM   (3 * STAGE_U32 * 4)       // 98304 bytes

__global__ __launch_bounds__(256, 2) void mma_gemm(
    const uint32_t* __restrict__ Af, const uint32_t* __restrict__ Bp,
    const float* __restrict__ bias, void* __restrict__ Cv,
    int Nn, int K, int Kdst, int col_off,
    float scale, int do_relu, int mode)
{
    extern __shared__ uint32_t S[];
    const uint32_t sbase = smem_u32(S);
    const int tid  = threadIdx.x;
    const int lane = tid & 31;
    const int wid  = tid >> 5;
    const int g    = lane >> 2;
    const int tig  = lane & 3;
    const int wm   = wid >> 2;   // 0..1
    const int wn   = wid & 3;    // 0..3
    const int bm   = blockIdx.y * BM;
    const int bn   = blockIdx.x * BN;
    const int T    = K >> 5;
    const int rt0  = bm >> 4;    // first row-tile

    const uint32_t* Bg = Bp + (size_t)blockIdx.x * K * 128;
    const int Kd8 = K >> 3;

    float acc[4][4][4];
#pragma unroll
    for (int i = 0; i < 4; i++)
#pragma unroll
        for (int j = 0; j < 4; j++)
#pragma unroll
            for (int r = 0; r < 4; r++) acc[i][j][r] = 0.f;

    auto CPA = [&](int t, int s) {
        const uint32_t dstA = sbase + (uint32_t)(s * STAGE_U32) * 4;
        const uint32_t dstB = dstA + A_STAGE_U32 * 4;
#pragma unroll
        for (int i = 0; i < 4; i++) {
            const int f  = tid + i * 256;           // 0..1023
            const int mt = f >> 7;                  // row-tile 0..7
            const int sl = f & 127;                 // 16B slot in 2KB chunk
            const uint32_t* srcA = Af + ((size_t)(rt0 + mt) * Kd8 + t * 4) * 128
                                      + sl * 4;
            asm volatile("cp.async.cg.shared.global [%0], [%1], 16;"
                         :: "r"(dstA + (uint32_t)f * 16), "l"(srcA) : "memory");
        }
        const uint32_t* srcB = Bg + (size_t)t * 4096 + tid * 4;
#pragma unroll
        for (int i = 0; i < 4; i++) {
            asm volatile("cp.async.cg.shared.global [%0], [%1], 16;"
                         :: "r"(dstB + (uint32_t)(tid + i * 256) * 16),
                            "l"(srcB + i * 1024) : "memory");
        }
    };
    auto COMPUTE = [&](int s) {
        const uint32_t* As = S + s * STAGE_U32;
        const uint32_t* Bs = As + A_STAGE_U32;
#pragma unroll
        for (int kt = 0; kt < 4; kt++) {
            uint4 af[4];
            uint2 bf[4];
#pragma unroll
            for (int mi = 0; mi < 4; mi++)
                af[mi] = *(const uint4*)(As + (wm * 4 + mi) * 512 + kt * 128
                                            + lane * 4);
#pragma unroll
            for (int ni = 0; ni < 4; ni++)
                bf[ni] = *(const uint2*)(Bs + ((wn * 4 + ni) * 4 + kt) * 64
                                            + lane * 2);
#pragma unroll
            for (int mi = 0; mi < 4; mi++)
#pragma unroll
                for (int ni = 0; ni < 4; ni++)
                    mma_tf32(acc[mi][ni], af[mi], bf[ni].x, bf[ni].y);
        }
    };

    // prologue: stages 0 and 1 in flight
    CPA(0, 0);
    asm volatile("cp.async.commit_group;" ::: "memory");
    CPA(1, 1);
    asm volatile("cp.async.commit_group;" ::: "memory");
    asm volatile("cp.async.wait_group 1;" ::: "memory");   // stage 0 ready
    __syncthreads();                                       // ... for everyone

    for (int t = 0; t < T; t++) {
        COMPUTE(t % 3);
        // refill the stage just retired ((t+2)%3 == (t-1)%3): all threads
        // passed the barrier after computing it, so overwrite is safe.
        if (t + 2 < T) CPA(t + 2, (t + 2) % 3);
        asm volatile("cp.async.commit_group;" ::: "memory");
        // stage t+1's group (committed at t-1) is older than the newest 1:
        asm volatile("cp.async.wait_group 1;" ::: "memory");
        __syncthreads();
    }

    // ---- epilogue ----
    if (mode == 0) {
        float* C = (float*)Cv;
#pragma unroll
        for (int mi = 0; mi < 4; mi++) {
            const int r0 = bm + (wm * 4 + mi) * 16 + g;
#pragma unroll
            for (int ni = 0; ni < 4; ni++) {
                const int c = bn + (wn * 4 + ni) * 8 + tig * 2;
                if (c < Nn) {
                    const float2 bv = *(const float2*)(bias + c);
                    float2 v0, v1;
                    v0.x = (acc[mi][ni][0] + bv.x) * scale;
                    v0.y = (acc[mi][ni][1] + bv.y) * scale;
                    v1.x = (acc[mi][ni][2] + bv.x) * scale;
                    v1.y = (acc[mi][ni][3] + bv.y) * scale;
                    if (do_relu) {
                        v0.x = fmaxf(v0.x, 0.f); v0.y = fmaxf(v0.y, 0.f);
                        v1.x = fmaxf(v1.x, 0.f); v1.y = fmaxf(v1.y, 0.f);
                    }
                    *(float2*)(C + (size_t)r0 * Kdst + col_off + c) = v0;
                    *(float2*)(C + (size_t)(r0 + 8) * Kdst + col_off + c) = v1;
                }
            }
        }
    } else if (mode == 1) {
        uint32_t* Cu = (uint32_t*)Cv;
#pragma unroll
        for (int mi = 0; mi < 4; mi++) {
            const int r0 = bm + (wm * 4 + mi) * 16 + g;
#pragma unroll
            for (int ni = 0; ni < 4; ni++) {
                const int c = bn + (wn * 4 + ni) * 8 + tig * 2;
                if (c < Nn) {
                    const float2 bv = *(const float2*)(bias + c);
                    float v0 = (acc[mi][ni][0] + bv.x) * scale;
                    float v1 = (acc[mi][ni][1] + bv.y) * scale;
                    float v2 = (acc[mi][ni][2] + bv.x) * scale;
                    float v3 = (acc[mi][ni][3] + bv.y) * scale;
                    if (do_relu) {
                        v0 = fmaxf(v0, 0.f); v1 = fmaxf(v1, 0.f);
                        v2 = fmaxf(v2, 0.f); v3 = fmaxf(v3, 0.f);
                    }
                    const int cc = col_off + c;
                    Cu[afrag_addr(r0,     cc,     Kdst)] = f32_tf32(v0);
                    Cu[afrag_addr(r0,     cc + 1, Kdst)] = f32_tf32(v1);
                    Cu[afrag_addr(r0 + 8, cc,     Kdst)] = f32_tf32(v2);
                    Cu[afrag_addr(r0 + 8, cc + 1, Kdst)] = f32_tf32(v3);
                }
            }
        }
    } else {
        uint32_t* Cu = (uint32_t*)Cv;
        auto store_frag = [&](int r, int cc, float v) {
            const int b = r >> 10, seq = r & 1023;
            const int h = cc >> 6, d = cc & 63;
            const uint32_t base = (uint32_t)(b * 16 + h) * 65536u;
            uint32_t addr;
            if (mode == 2) {          // Q: A-frag
                addr = base + (uint32_t)((seq >> 4) * 8 + (d >> 3)) * 128u
                     + (uint32_t)((seq & 7) * 4 + (d & 3)) * 4u
                     + (uint32_t)(((seq >> 3) & 1) + 2 * ((d >> 2) & 1));
            } else if (mode == 3) {   // K: B-frag, permuted key columns
                const uint32_t j = (uint32_t)(((seq & 3) << 1) | ((seq >> 2) & 1));
                addr = base + (uint32_t)((seq >> 3) * 8 + (d >> 3)) * 64u
                     + (j * 4 + (uint32_t)(d & 3)) * 2u + (uint32_t)((d >> 2) & 1);
            } else {                  // V: B-frag, natural order
                addr = base + (uint32_t)((seq >> 3) * 8 + (d >> 3)) * 64u
                     + (uint32_t)((d & 7) * 4 + (seq & 3)) * 2u
                     + (uint32_t)((seq >> 2) & 1);
            }
            Cu[addr] = f32_tf32(v);
        };
#pragma unroll
        for (int mi = 0; mi < 4; mi++) {
            const int r0 = bm + (wm * 4 + mi) * 16 + g;
#pragma unroll
            for (int ni = 0; ni < 4; ni++) {
                const int c = bn + (wn * 4 + ni) * 8 + tig * 2;
                const float2 bv = *(const float2*)(bias + c);
                store_frag(r0,     c,     (acc[mi][ni][0] + bv.x) * scale);
                store_frag(r0,     c + 1, (acc[mi][ni][1] + bv.y) * scale);
                store_frag(r0 + 8, c,     (acc[mi][ni][2] + bv.x) * scale);
                store_frag(r0 + 8, c + 1, (acc[mi][ni][3] + bv.y) * scale);
            }
        }
    }
}

// ---------------------------------------------------------------------------
// Flash attention via tf32 mma.sync; epilogue stores A-frag tf32 into CATF.
// (unchanged structure from R8/R10 — its pipeline already waits before the
//  barrier.)
// ---------------------------------------------------------------------------
#define ATT_SMEM (2 * 16384 * 4)      // 131072 B

__global__ __launch_bounds__(256, 1) void attn_mma(
    const uint32_t* __restrict__ Qf, const uint32_t* __restrict__ Kf,
    const uint32_t* __restrict__ Vf, uint32_t* __restrict__ OUT)
{
    extern __shared__ uint32_t S[];   // [2][K 8192 | V 8192]
    const uint32_t sbase = smem_u32(S);
    const int tid  = threadIdx.x;
    const int lane = tid & 31;
    const int w    = tid >> 5;
    const int g    = lane >> 2;
    const int tig  = lane & 3;
    const int qb   = blockIdx.x;
    const int bh   = blockIdx.y;

    const uint32_t* Qb = Qf + (size_t)bh * 65536;
    const uint32_t* Kb = Kf + (size_t)bh * 65536;
    const uint32_t* Vb = Vf + (size_t)bh * 65536;

    uint4 qf[8];
    {
        const uint32_t* qp = Qb + (size_t)((qb * 8 + w) * 8) * 128 + lane * 4;
#pragma unroll
        for (int ks = 0; ks < 8; ks++)
            qf[ks] = *(const uint4*)(qp + ks * 128);
    }

    float o[8][4];
#pragma unroll
    for (int dt = 0; dt < 8; dt++)
#pragma unroll
        for (int r = 0; r < 4; r++) o[dt][r] = 0.f;
    float m0 = -1e30f, m1 = -1e30f, l0 = 0.f, l1 = 0.f;

    auto CPA = [&](int t, int s) {
        const uint32_t kd = sbase + (uint32_t)(s * 16384) * 4 + tid * 16;
        const uint32_t vd = kd + 8192 * 4;
        const uint32_t* ks_ = Kb + (size_t)t * 8192 + tid * 4;
        const uint32_t* vs_ = Vb + (size_t)t * 8192 + tid * 4;
#pragma unroll
        for (int i = 0; i < 8; i++) {
            asm volatile("cp.async.cg.shared.global [%0], [%1], 16;"
                         :: "r"(kd + i * 4096u), "l"(ks_ + i * 1024) : "memory");
            asm volatile("cp.async.cg.shared.global [%0], [%1], 16;"
                         :: "r"(vd + i * 4096u), "l"(vs_ + i * 1024) : "memory");
        }
    };

    CPA(0, 0);
    asm volatile("cp.async.commit_group;" ::: "memory");

    for (int t = 0; t < 8; t++) {
        const int s = t & 1;
        asm volatile("cp.async.wait_group 0;" ::: "memory");
        __syncthreads();
        if (t + 1 < 8) {
            CPA(t + 1, s ^ 1);
            asm volatile("cp.async.commit_group;" ::: "memory");
        }
        const uint32_t* Ksm = S + s * 16384;
        const uint32_t* Vsm = Ksm + 8192;

        float sc[16][4];
#pragma unroll
        for (int nt = 0; nt < 16; nt++) {
            sc[nt][0] = 0.f; sc[nt][1] = 0.f; sc[nt][2] = 0.f; sc[nt][3] = 0.f;
#pragma unroll
            for (int ks = 0; ks < 8; ks++) {
                const uint2 b = *(const uint2*)(Ksm + (nt * 8 + ks) * 64 + lane * 2);
                mma_tf32(sc[nt], qf[ks], b.x, b.y);
            }
        }

        if (t == qb) {
            const int q0 = w * 16 + g;
#pragma unroll
            for (int nt = 0; nt < 16; nt++) {
                const int k0 = nt * 8 + tig;
                if (k0     == q0)     sc[nt][0] = -1e30f;
                if (k0 + 4 == q0)     sc[nt][1] = -1e30f;
                if (k0     == q0 + 8) sc[nt][2] = -1e30f;
                if (k0 + 4 == q0 + 8) sc[nt][3] = -1e30f;
            }
        }

        float mt0 = -1e30f, mt1 = -1e30f;
#pragma unroll
        for (int nt = 0; nt < 16; nt++) {
            mt0 = fmaxf(mt0, fmaxf(sc[nt][0], sc[nt][1]));
            mt1 = fmaxf(mt1, fmaxf(sc[nt][2], sc[nt][3]));
        }
        mt0 = fmaxf(mt0, __shfl_xor_sync(0xFFFFFFFFu, mt0, 1));
        mt0 = fmaxf(mt0, __shfl_xor_sync(0xFFFFFFFFu, mt0, 2));
        mt1 = fmaxf(mt1, __shfl_xor_sync(0xFFFFFFFFu, mt1, 1));
        mt1 = fmaxf(mt1, __shfl_xor_sync(0xFFFFFFFFu, mt1, 2));
        const float nm0 = fmaxf(m0, mt0), nm1 = fmaxf(m1, mt1);
        const float cr0 = exp2f((m0 - nm0) * L2E);
        const float cr1 = exp2f((m1 - nm1) * L2E);
        m0 = nm0; m1 = nm1;
        l0 *= cr0; l1 *= cr1;
#pragma unroll
        for (int dt = 0; dt < 8; dt++) {
            o[dt][0] *= cr0; o[dt][1] *= cr0;
            o[dt][2] *= cr1; o[dt][3] *= cr1;
        }
        const float b0 = nm0 * L2E, b1 = nm1 * L2E;
#pragma unroll
        for (int nt = 0; nt < 16; nt++) {
            const float p0 = exp2f(fmaf(sc[nt][0], L2E, -b0));
            const float p1 = exp2f(fmaf(sc[nt][1], L2E, -b0));
            const float p2 = exp2f(fmaf(sc[nt][2], L2E, -b1));
            const float p3 = exp2f(fmaf(sc[nt][3], L2E, -b1));
            l0 += p0 + p1; l1 += p2 + p3;
            sc[nt][0] = __uint_as_float(f32_tf32(p0));
            sc[nt][1] = __uint_as_float(f32_tf32(p2));
            sc[nt][2] = __uint_as_float(f32_tf32(p1));
            sc[nt][3] = __uint_as_float(f32_tf32(p3));
        }

#pragma unroll
        for (int kk = 0; kk < 16; kk++) {
            const uint4 a = make_uint4(__float_as_uint(sc[kk][0]),
                                       __float_as_uint(sc[kk][1]),
                                       __float_as_uint(sc[kk][2]),
                                       __float_as_uint(sc[kk][3]));
#pragma unroll
            for (int dt = 0; dt < 8; dt++) {
                const uint2 b = *(const uint2*)(Vsm + (kk * 8 + dt) * 64 + lane * 2);
                mma_tf32(o[dt], a, b.x, b.y);
            }
        }
    }

    l0 += __shfl_xor_sync(0xFFFFFFFFu, l0, 1);
    l0 += __shfl_xor_sync(0xFFFFFFFFu, l0, 2);
    l1 += __shfl_xor_sync(0xFFFFFFFFu, l1, 1);
    l1 += __shfl_xor_sync(0xFFFFFFFFu, l1, 2);
    const float inv0 = 1.f / l0, inv1 = 1.f / l1;

    // fragment-major store into CATF (width 1088)
    const int b_ = bh >> 4, h = bh & 15;
    const int r0 = b_ * 1024 + qb * 128 + w * 16 + g;
    const int r1 = r0 + 8;
#pragma unroll
    for (int dt = 0; dt < 8; dt++) {
        const int cc = h * 64 + dt * 8 + tig * 2;
        OUT[afrag_addr(r0, cc,     CATD)] = f32_tf32(o[dt][0] * inv0);
        OUT[afrag_addr(r0, cc + 1, CATD)] = f32_tf32(o[dt][1] * inv0);
        OUT[afrag_addr(r1, cc,     CATD)] = f32_tf32(o[dt][2] * inv1);
        OUT[afrag_addr(r1, cc + 1, CATD)] = f32_tf32(o[dt][3] * inv1);
    }
}

// ---------------------------------------------------------------------------
// launch
// ---------------------------------------------------------------------------
extern "C" void kernel_launch(void* const* d_in, const int* in_sizes, int n_in,
                              void* d_out, int out_size)
{
    const float* x    = (const float*)d_in[0];
    const float* Wq   = (const float*)d_in[1];
    const float* bq   = (const float*)d_in[2];
    const float* Wk   = (const float*)d_in[3];
    const float* bk   = (const float*)d_in[4];
    const float* Wv   = (const float*)d_in[5];
    const float* bv   = (const float*)d_in[6];
    const float* Win  = (const float*)d_in[7];
    const float* bin_ = (const float*)d_in[8];
    const float* W1   = (const float*)d_in[9];
    const float* b1   = (const float*)d_in[10];
    const float* W2   = (const float*)d_in[11];
    const float* b2   = (const float*)d_in[12];
    float* out = (float*)d_out;

    uint32_t *xf, *catf, *h1f, *wp, *qf, *kf, *vf;
    cudaGetSymbolAddress((void**)&xf,   g_XF);
    cudaGetSymbolAddress((void**)&catf, g_CATF);
    cudaGetSymbolAddress((void**)&h1f,  g_H1F);
    cudaGetSymbolAddress((void**)&wp,   g_WP);
    cudaGetSymbolAddress((void**)&qf,   g_QF);
    cudaGetSymbolAddress((void**)&kf,   g_KF);
    cudaGetSymbolAddress((void**)&vf,   g_VF);

    cudaFuncSetAttribute(mma_gemm, cudaFuncAttributeMaxDynamicSharedMemorySize,
                         GEMM_SMEM);
    cudaFuncSetAttribute(attn_mma, cudaFuncAttributeMaxDynamicSharedMemorySize,
                         ATT_SMEM);

    // ---- input/weight permutation (fragment-major tf32) ----
    permute_x<<<(MTOT * DIM / 4) / 256, 256>>>(x, xf, DIM);
    permute_w<<<(1024 * 1024 / 4) / 256, 256>>>(Wq,  wp + WP_Q,  1024, 1024, 1024);
    permute_w<<<(1024 * 1024 / 4) / 256, 256>>>(Wk,  wp + WP_K,  1024, 1024, 1024);
    permute_w<<<(1024 * 1024 / 4) / 256, 256>>>(Wv,  wp + WP_V,  1024, 1024, 1024);
    permute_w<<<(1024 * 128  / 4) / 256, 256>>>(Win, wp + WP_IN, 1024, 64,   128);
    permute_w<<<(1088 * 2048 / 4) / 256, 256>>>(W1,  wp + WP_1,  1088, 2048, 2048);
    permute_w<<<(2048 * 1024 / 4) / 256, 256>>>(W2,  wp + WP_2,  2048, 1024, 1024);

    const float scaling = 0.125f;   // HEAD_DIM^-0.5
    dim3 blk(256);

    // Q/K/V projections -> fragment-major tf32 scratch (Q pre-scaled)
    dim3 g_qkv(DIM / BN, MTOT / BM);          // (8, 64)
    mma_gemm<<<g_qkv, blk, GEMM_SMEM>>>(xf, wp + WP_Q, bq, qf, DIM, DIM, 0, 0, scaling, 0, 2);
    mma_gemm<<<g_qkv, blk, GEMM_SMEM>>>(xf, wp + WP_K, bk, kf, DIM, DIM, 0, 0, 1.0f, 0, 3);
    mma_gemm<<<g_qkv, blk, GEMM_SMEM>>>(xf, wp + WP_V, bv, vf, DIM, DIM, 0, 0, 1.0f, 0, 4);

    // in_ projection -> CATF columns [1024, 1088) (A-frag store)
    dim3 g_in(1, MTOT / BM);                  // (1, 64)
    mma_gemm<<<g_in, blk, GEMM_SMEM>>>(xf, wp + WP_IN, bin_, catf, HDIM, DIM, CATD, DIM, 1.0f, 0, 1);

    // flash attention (tensor cores) -> CATF columns [0, 1024)
    dim3 g_att(8, BSZ * NHEAD);               // (8, 128)
    attn_mma<<<g_att, blk, ATT_SMEM>>>(qf, kf, vf, catf);

    // FFN1: CATF @ W1 -> H1F (A-frag store, relu)
    dim3 g_f1(FFD / BN, MTOT / BM);           // (16, 64)
    mma_gemm<<<g_f1, blk, GEMM_SMEM>>>(catf, wp + WP_1, b1, h1f, FFD, CATD, FFD, 0, 1.0f, 1, 1);

    // FFN2: H1F @ W2 -> out (standard float)
    dim3 g_f2(DIM / BN, MTOT / BM);           // (8, 64)
    mma_gemm<<<g_f2, blk, GEMM_SMEM>>>(h1f, wp + WP_2, b2, out, DIM, FFD, DIM, 0, 1.0f, 0, 0);
}

// round 16
// speedup vs baseline: 2.0721x; 1.8622x over previous
#include <cuda_runtime.h>
#include <cuda_fp16.h>
#include <cstdint>
#include <cstddef>

// ---------------------------------------------------------------------------
// Problem constants
// ---------------------------------------------------------------------------
#define BSZ       8
#define SEQ       1024
#define DIM       1024
#define NHEAD     16
#define HDIM      64
#define MTOT      (BSZ * SEQ)        // 8192
#define CATD      (DIM + HDIM)       // 1088
#define FFD       (2 * DIM)          // 2048
#define L2E       1.4426950408889634f

// ---------------------------------------------------------------------------
// Scratch (static device globals; no allocation anywhere)
// ---------------------------------------------------------------------------
// fp16 A-fragment-major activations (m16n8k16 A operand), u32 = half2 (lo=even k):
//   u32 idx(r,k,Kd) = ((r>>4)*(Kd>>4)+(k>>4))*128 + ((r&7)*4+((k&7)>>1))*4
//                   + ((r>>3)&1) + 2*((k>>3)&1);  half = k&1
__device__ uint32_t g_XF  [(size_t)MTOT * DIM  / 2];
__device__ uint32_t g_CATF[(size_t)MTOT * CATD / 2];
__device__ uint32_t g_H1F [(size_t)MTOT * FFD  / 2];

// fp16 fragment-major Q/K/V per (b,h): 32768 u32 each, 128 bh slots.
//  Q: [qt 64][kt 4][lane 32][reg 4]   (A-frags, rows=query, k=d)
//  K: [nt 128][kt 4][lane 32][reg 2]  (B-frags for S=Q.K^T, natural key order)
//  V: [kk 64][dt 8][lane 32][reg 2]   (B-frags for O=P.V)
__device__ uint32_t g_QF[(size_t)128 * 32768];
__device__ uint32_t g_KF[(size_t)128 * 32768];
__device__ uint32_t g_VF[(size_t)128 * 32768];

// Pre-permuted fp16 weights (B-frag-major, 128-wide N panels). u32 offsets.
#define WP_Q   0
#define WP_K   524288
#define WP_V   1048576
#define WP_IN  1572864
#define WP_1   1638400
#define WP_2   2752512
#define WP_TOT 3801088
__device__ uint32_t g_WP[WP_TOT];

// ---------------------------------------------------------------------------
// helpers
// ---------------------------------------------------------------------------
__device__ __forceinline__ uint32_t smem_u32(const void* p) {
    uint32_t a;
    asm("{ .reg .u64 t; cvta.to.shared.u64 t, %1; cvt.u32.u64 %0, t; }"
        : "=r"(a) : "l"(p));
    return a;
}
__device__ __forceinline__ uint32_t pack_h2(float lo, float hi) {
    const __half2 h = __floats2half2_rn(lo, hi);   // .x = lo bits
    return *(const uint32_t*)&h;
}
__device__ __forceinline__ void mma_f16(float* c, uint4 a, uint32_t b0, uint32_t b1) {
    asm volatile(
        "mma.sync.aligned.m16n8k16.row.col.f32.f16.f16.f32 "
        "{%0,%1,%2,%3}, {%4,%5,%6,%7}, {%8,%9}, {%0,%1,%2,%3};"
        : "+f"(c[0]), "+f"(c[1]), "+f"(c[2]), "+f"(c[3])
        : "r"(a.x), "r"(a.y), "r"(a.z), "r"(a.w), "r"(b0), "r"(b1));
}
// u32 index of (r,k) pair-slot in A-frag-major layout (k even selects the u32)
__device__ __forceinline__ uint32_t afrag16(int r, int k, int Kd) {
    return (uint32_t)(((r >> 4) * (Kd >> 4) + (k >> 4)) * 128
                    + ((r & 7) * 4 + ((k & 7) >> 1)) * 4
                    + ((r >> 3) & 1) + 2 * ((k >> 3) & 1));
}
// u32 index of (k,n) pair-slot in B-frag weight panel (panel = 128 n cols)
__device__ __forceinline__ uint32_t wfrag16(int k, int n, int K) {
    return (uint32_t)((n >> 7) * (K >> 5) * 2048 + (k >> 5) * 2048
                    + (((n >> 3) & 15) * 2 + ((k >> 4) & 1)) * 64
                    + ((n & 7) * 4 + ((k & 7) >> 1)) * 2 + ((k >> 3) & 1));
}

// ---------------------------------------------------------------------------
// x -> fp16 A-fragment-major
// ---------------------------------------------------------------------------
__global__ void permute_x(const float* __restrict__ X, uint32_t* __restrict__ Xf,
                          int Kd)
{
    const int idx = blockIdx.x * 256 + threadIdx.x;   // float4 id
    const int r  = idx / (Kd >> 2);
    const int k4 = (idx - r * (Kd >> 2)) << 2;
    const float4 v = *(const float4*)(X + (size_t)r * Kd + k4);
    Xf[afrag16(r, k4,     Kd)] = pack_h2(v.x, v.y);
    Xf[afrag16(r, k4 + 2, Kd)] = pack_h2(v.z, v.w);
}

// ---------------------------------------------------------------------------
// W[k][n] -> fp16 B-frag-major panels. Thread: 2 k-rows x 4 n.
// ---------------------------------------------------------------------------
__global__ void permute_w(const float* __restrict__ W, uint32_t* __restrict__ Wp,
                          int K, int Nn, int Npad)
{
    const int idx = blockIdx.x * 256 + threadIdx.x;
    const int rowlen4 = Npad >> 2;
    const int k2 = idx / rowlen4;
    if (k2 >= (K >> 1)) return;
    const int k  = k2 << 1;
    const int n4 = (idx - k2 * rowlen4) << 2;

    float4 v0 = make_float4(0.f, 0.f, 0.f, 0.f);
    float4 v1 = make_float4(0.f, 0.f, 0.f, 0.f);
    if (n4 < Nn) {
        v0 = *(const float4*)(W + (size_t)k * Nn + n4);
        v1 = *(const float4*)(W + (size_t)(k + 1) * Nn + n4);
    }
    Wp[wfrag16(k, n4 + 0, K)] = pack_h2(v0.x, v1.x);
    Wp[wfrag16(k, n4 + 1, K)] = pack_h2(v0.y, v1.y);
    Wp[wfrag16(k, n4 + 2, K)] = pack_h2(v0.z, v1.z);
    Wp[wfrag16(k, n4 + 3, K)] = pack_h2(v0.w, v1.w);
}

// ---------------------------------------------------------------------------
// fp16 mma.sync GEMM, both operands pre-fragmented in gmem.
//   128x128 block, BK=32 (2 k16 tiles), 8 warps (2x4), 64x32 warp tiles,
//   3-stage cp.async ring (R15 pipeline: compute -> prefetch -> wait -> bar).
//   mode 0: float store   1: A-frag store (Kdst, col_off)
//   2/3/4: Q/K/V scatter
// ---------------------------------------------------------------------------
#define BM 128
#define BN 128
#define A_STAGE_U32 2048
#define B_STAGE_U32 2048
#define STAGE_U32   4096
#define GEMM_SMEM   (3 * STAGE_U32 * 4)       // 49152 bytes

__global__ __launch_bounds__(256, 2) void mma_gemm(
    const uint32_t* __restrict__ Af, const uint32_t* __restrict__ Bp,
    const float* __restrict__ bias, void* __restrict__ Cv,
    int Nn, int K, int Kdst, int col_off,
    float scale, int do_relu, int mode)
{
    extern __shared__ uint32_t S[];
    const uint32_t sbase = smem_u32(S);
    const int tid  = threadIdx.x;
    const int lane = tid & 31;
    const int wid  = tid >> 5;
    const int g    = lane >> 2;
    const int tig  = lane & 3;
    const int wm   = wid >> 2;   // 0..1
    const int wn   = wid & 3;    // 0..3
    const int bm   = blockIdx.y * BM;
    const int bn   = blockIdx.x * BN;
    const int T    = K >> 5;
    const int rt0  = bm >> 4;
    const int Kt   = K >> 4;     // k16-tile count

    const uint32_t* Bg = Bp + (size_t)blockIdx.x * (K >> 5) * 2048;

    float acc[4][4][4];
#pragma unroll
    for (int i = 0; i < 4; i++)
#pragma unroll
        for (int j = 0; j < 4; j++)
#pragma unroll
            for (int r = 0; r < 4; r++) acc[i][j][r] = 0.f;

    auto CPA = [&](int t, int s) {
        const uint32_t dstA = sbase + (uint32_t)(s * STAGE_U32) * 4;
        const uint32_t dstB = dstA + A_STAGE_U32 * 4;
        // A: 512 16B-slots; tile = slot>>5 (mt*2+kt), within = slot&31
#pragma unroll
        for (int i = 0; i < 2; i++) {
            const int slot = tid + i * 256;
            const int tile = slot >> 5;            // 0..15
            const int mt   = tile >> 1;
            const int kt   = tile & 1;
            const uint32_t* srcA = Af + ((size_t)(rt0 + mt) * Kt + 2 * t + kt) * 128
                                      + (slot & 31) * 4;
            asm volatile("cp.async.cg.shared.global [%0], [%1], 16;"
                         :: "r"(dstA + (uint32_t)slot * 16), "l"(srcA) : "memory");
        }
        // B: contiguous 2048 u32
        const uint32_t* srcB = Bg + (size_t)t * 2048 + tid * 4;
#pragma unroll
        for (int i = 0; i < 2; i++) {
            asm volatile("cp.async.cg.shared.global [%0], [%1], 16;"
                         :: "r"(dstB + (uint32_t)(tid + i * 256) * 16),
                            "l"(srcB + i * 1024) : "memory");
        }
    };
    auto COMPUTE = [&](int s) {
        const uint32_t* As = S + s * STAGE_U32;
        const uint32_t* Bs = As + A_STAGE_U32;
#pragma unroll
        for (int kt = 0; kt < 2; kt++) {
            uint4 af[4];
            uint2 bf[4];
#pragma unroll
            for (int mi = 0; mi < 4; mi++)
                af[mi] = *(const uint4*)(As + ((wm * 4 + mi) * 2 + kt) * 128
                                            + lane * 4);
#pragma unroll
            for (int ni = 0; ni < 4; ni++)
                bf[ni] = *(const uint2*)(Bs + ((wn * 4 + ni) * 2 + kt) * 64
                                            + lane * 2);
#pragma unroll
            for (int mi = 0; mi < 4; mi++)
#pragma unroll
                for (int ni = 0; ni < 4; ni++)
                    mma_f16(acc[mi][ni], af[mi], bf[ni].x, bf[ni].y);
        }
    };

    CPA(0, 0);
    asm volatile("cp.async.commit_group;" ::: "memory");
    CPA(1, 1);
    asm volatile("cp.async.commit_group;" ::: "memory");
    asm volatile("cp.async.wait_group 1;" ::: "memory");
    __syncthreads();

    for (int t = 0; t < T; t++) {
        COMPUTE(t % 3);
        if (t + 2 < T) CPA(t + 2, (t + 2) % 3);
        asm volatile("cp.async.commit_group;" ::: "memory");
        asm volatile("cp.async.wait_group 1;" ::: "memory");
        __syncthreads();
    }

    // ---- epilogue ----
    if (mode == 0) {
        float* C = (float*)Cv;
#pragma unroll
        for (int mi = 0; mi < 4; mi++) {
            const int r0 = bm + (wm * 4 + mi) * 16 + g;
#pragma unroll
            for (int ni = 0; ni < 4; ni++) {
                const int c = bn + (wn * 4 + ni) * 8 + tig * 2;
                if (c < Nn) {
                    const float2 bv = *(const float2*)(bias + c);
                    float2 v0, v1;
                    v0.x = (acc[mi][ni][0] + bv.x) * scale;
                    v0.y = (acc[mi][ni][1] + bv.y) * scale;
                    v1.x = (acc[mi][ni][2] + bv.x) * scale;
                    v1.y = (acc[mi][ni][3] + bv.y) * scale;
                    if (do_relu) {
                        v0.x = fmaxf(v0.x, 0.f); v0.y = fmaxf(v0.y, 0.f);
                        v1.x = fmaxf(v1.x, 0.f); v1.y = fmaxf(v1.y, 0.f);
                    }
                    *(float2*)(C + (size_t)r0 * Kdst + col_off + c) = v0;
                    *(float2*)(C + (size_t)(r0 + 8) * Kdst + col_off + c) = v1;
                }
            }
        }
    } else if (mode == 1) {
        uint32_t* Cu = (uint32_t*)Cv;
#pragma unroll
        for (int mi = 0; mi < 4; mi++) {
            const int r0 = bm + (wm * 4 + mi) * 16 + g;    // bit3 of r0%16 == 0
#pragma unroll
            for (int ni = 0; ni < 4; ni++) {
                const int c = bn + (wn * 4 + ni) * 8 + tig * 2;
                if (c < Nn) {
                    const float2 bv = *(const float2*)(bias + c);
                    float v0 = (acc[mi][ni][0] + bv.x) * scale;
                    float v1 = (acc[mi][ni][1] + bv.y) * scale;
                    float v2 = (acc[mi][ni][2] + bv.x) * scale;
                    float v3 = (acc[mi][ni][3] + bv.y) * scale;
                    if (do_relu) {
                        v0 = fmaxf(v0, 0.f); v1 = fmaxf(v1, 0.f);
                        v2 = fmaxf(v2, 0.f); v3 = fmaxf(v3, 0.f);
                    }
                    const int cc = col_off + c;
                    uint2 w;
                    w.x = pack_h2(v0, v1);     // rows r0
                    w.y = pack_h2(v2, v3);     // rows r0+8 -> reg+1
                    *(uint2*)(Cu + afrag16(r0, cc, Kdst)) = w;
                }
            }
        }
    } else if (mode == 2 || mode == 3) {
        uint32_t* Cu = (uint32_t*)Cv;
#pragma unroll
        for (int mi = 0; mi < 4; mi++) {
            const int r0 = bm + (wm * 4 + mi) * 16 + g;
            const int b  = r0 >> 10, seq = r0 & 1023;
#pragma unroll
            for (int ni = 0; ni < 4; ni++) {
                const int c = bn + (wn * 4 + ni) * 8 + tig * 2;
                const int h = c >> 6, d = c & 63;
                const float2 bv = *(const float2*)(bias + c);
                const float v0 = (acc[mi][ni][0] + bv.x) * scale;
                const float v1 = (acc[mi][ni][1] + bv.y) * scale;
                const float v2 = (acc[mi][ni][2] + bv.x) * scale;
                const float v3 = (acc[mi][ni][3] + bv.y) * scale;
                const uint32_t base = (uint32_t)(b * 16 + h) * 32768u;
                if (mode == 2) {      // Q A-frag: rows seq/seq+8 -> reg/reg+1
                    const uint32_t idx = base
                        + (uint32_t)((seq >> 4) * 4 + (d >> 4)) * 128u
                        + (uint32_t)((seq & 7) * 4 + ((d & 7) >> 1)) * 4u
                        + 2u * (uint32_t)((d >> 3) & 1);
                    uint2 w; w.x = pack_h2(v0, v1); w.y = pack_h2(v2, v3);
                    *(uint2*)(Cu + idx) = w;
                } else {              // K B-frag: key=seq (n), d (k)
                    const uint32_t i0 = base
                        + (uint32_t)((seq >> 3) * 4 + (d >> 4)) * 64u
                        + (uint32_t)((seq & 7) * 4 + ((d & 7) >> 1)) * 2u
                        + (uint32_t)((d >> 3) & 1);
                    Cu[i0]        = pack_h2(v0, v1);
                    Cu[i0 + 256u] = pack_h2(v2, v3);   // seq+8 -> nt+1
                }
            }
        }
    } else {                          // V B-frag: key=seq (k), d (n); half stores
        __half* Hc = (__half*)Cv;
#pragma unroll
        for (int mi = 0; mi < 4; mi++) {
            const int r0 = bm + (wm * 4 + mi) * 16 + g;
            const int b  = r0 >> 10, seq = r0 & 1023;
#pragma unroll
            for (int ni = 0; ni < 4; ni++) {
                const int c = bn + (wn * 4 + ni) * 8 + tig * 2;
                const int h = c >> 6, d = c & 63;
                const float2 bv = *(const float2*)(bias + c);
                const float v0 = (acc[mi][ni][0] + bv.x) * scale;
                const float v1 = (acc[mi][ni][1] + bv.y) * scale;
                const float v2 = (acc[mi][ni][2] + bv.x) * scale;
                const float v3 = (acc[mi][ni][3] + bv.y) * scale;
                const uint32_t base = (uint32_t)(b * 16 + h) * 32768u;
                const uint32_t kkdt = (uint32_t)((seq >> 4) * 8 + (d >> 3)) * 64u;
                const uint32_t l0 = (uint32_t)((d & 7) * 4 + ((seq & 7) >> 1)) * 2u;
                const uint32_t hp = (uint32_t)(seq & 1);
                // (seq, d) / (seq, d+1): lane +4 -> u32 +8 ; (seq+8,*): reg +1
                const uint32_t i00 = base + kkdt + l0;
                Hc[(i00          ) * 2 + hp] = __float2half_rn(v0);
                Hc[(i00 + 8u     ) * 2 + hp] = __float2half_rn(v1);
                Hc[(i00 + 1u     ) * 2 + hp] = __float2half_rn(v2);
                Hc[(i00 + 9u     ) * 2 + hp] = __float2half_rn(v3);
            }
        }
    }
}

// ---------------------------------------------------------------------------
// Flash attention via fp16 mma.sync. 128 q/CTA, 8 warps, 128-key KV tiles,
// double-buffered cp.async. S frags repack directly as PV A-frags (natural
// key order with f16 D-frag column pairing). Output -> CATF (A-frag fp16).
// ---------------------------------------------------------------------------
#define ATT_SMEM (2 * 8192 * 4)       // 65536 B

__global__ __launch_bounds__(256, 1) void attn_mma(
    const uint32_t* __restrict__ Qf, const uint32_t* __restrict__ Kf,
    const uint32_t* __restrict__ Vf, uint32_t* __restrict__ OUT)
{
    extern __shared__ uint32_t S[];   // [2][K 4096 | V 4096]
    const uint32_t sbase = smem_u32(S);
    const int tid  = threadIdx.x;
    const int lane = tid & 31;
    const int w    = tid >> 5;
    const int g    = lane >> 2;
    const int tig  = lane & 3;
    const int qb   = blockIdx.x;
    const int bh   = blockIdx.y;

    const uint32_t* Qb = Qf + (size_t)bh * 32768;
    const uint32_t* Kb = Kf + (size_t)bh * 32768;
    const uint32_t* Vb = Vf + (size_t)bh * 32768;

    // Q frags: this warp's 16 queries = q-tile qb*8+w, 4 k16 tiles over d=64
    uint4 qf[4];
    {
        const uint32_t* qp = Qb + (size_t)(qb * 8 + w) * 512 + lane * 4;
#pragma unroll
        for (int kt = 0; kt < 4; kt++)
            qf[kt] = *(const uint4*)(qp + kt * 128);
    }

    float o[8][4];
#pragma unroll
    for (int dt = 0; dt < 8; dt++)
#pragma unroll
        for (int r = 0; r < 4; r++) o[dt][r] = 0.f;
    float m0 = -1e30f, m1 = -1e30f, l0 = 0.f, l1 = 0.f;

    auto CPA = [&](int t, int s) {
        const uint32_t kd = sbase + (uint32_t)(s * 8192) * 4 + tid * 16;
        const uint32_t vd = kd + 4096 * 4;
        const uint32_t* ks_ = Kb + (size_t)t * 4096 + tid * 4;
        const uint32_t* vs_ = Vb + (size_t)t * 4096 + tid * 4;
#pragma unroll
        for (int i = 0; i < 4; i++) {
            asm volatile("cp.async.cg.shared.global [%0], [%1], 16;"
                         :: "r"(kd + i * 4096u), "l"(ks_ + i * 1024) : "memory");
            asm volatile("cp.async.cg.shared.global [%0], [%1], 16;"
                         :: "r"(vd + i * 4096u), "l"(vs_ + i * 1024) : "memory");
        }
    };

    CPA(0, 0);
    asm volatile("cp.async.commit_group;" ::: "memory");

    for (int t = 0; t < 8; t++) {
        const int s = t & 1;
        asm volatile("cp.async.wait_group 0;" ::: "memory");
        __syncthreads();
        if (t + 1 < 8) {
            CPA(t + 1, s ^ 1);
            asm volatile("cp.async.commit_group;" ::: "memory");
        }
        const uint32_t* Ksm = S + s * 8192;
        const uint32_t* Vsm = Ksm + 4096;

        // S = Q.K^T : 16 n-tiles x 4 k16-steps
        float sc[16][4];
#pragma unroll
        for (int nt = 0; nt < 16; nt++) {
            sc[nt][0] = 0.f; sc[nt][1] = 0.f; sc[nt][2] = 0.f; sc[nt][3] = 0.f;
#pragma unroll
            for (int kt = 0; kt < 4; kt++) {
                const uint2 b = *(const uint2*)(Ksm + (nt * 4 + kt) * 64 + lane * 2);
                mma_f16(sc[nt], qf[kt], b.x, b.y);
            }
        }

        // diag mask: c0 col = nt*8+2tig, c1 +1; rows g / g+8
        if (t == qb) {
            const int q0 = w * 16 + g;
#pragma unroll
            for (int nt = 0; nt < 16; nt++) {
                const int k0 = nt * 8 + tig * 2;
                if (k0     == q0)     sc[nt][0] = -1e30f;
                if (k0 + 1 == q0)     sc[nt][1] = -1e30f;
                if (k0     == q0 + 8) sc[nt][2] = -1e30f;
                if (k0 + 1 == q0 + 8) sc[nt][3] = -1e30f;
            }
        }

        // online softmax
        float mt0 = -1e30f, mt1 = -1e30f;
#pragma unroll
        for (int nt = 0; nt < 16; nt++) {
            mt0 = fmaxf(mt0, fmaxf(sc[nt][0], sc[nt][1]));
            mt1 = fmaxf(mt1, fmaxf(sc[nt][2], sc[nt][3]));
        }
        mt0 = fmaxf(mt0, __shfl_xor_sync(0xFFFFFFFFu, mt0, 1));
        mt0 = fmaxf(mt0, __shfl_xor_sync(0xFFFFFFFFu, mt0, 2));
        mt1 = fmaxf(mt1, __shfl_xor_sync(0xFFFFFFFFu, mt1, 1));
        mt1 = fmaxf(mt1, __shfl_xor_sync(0xFFFFFFFFu, mt1, 2));
        const float nm0 = fmaxf(m0, mt0), nm1 = fmaxf(m1, mt1);
        const float cr0 = exp2f((m0 - nm0) * L2E);
        const float cr1 = exp2f((m1 - nm1) * L2E);
        m0 = nm0; m1 = nm1;
        l0 *= cr0; l1 *= cr1;
#pragma unroll
        for (int dt = 0; dt < 8; dt++) {
            o[dt][0] *= cr0; o[dt][1] *= cr0;
            o[dt][2] *= cr1; o[dt][3] *= cr1;
        }
        const float b0 = nm0 * L2E, b1 = nm1 * L2E;

        // P (fp16 A-frags): tile j from S n-tiles 2j, 2j+1
        uint4 pk[8];
#pragma unroll
        for (int j = 0; j < 8; j++) {
            const float p00 = exp2f(fmaf(sc[2*j][0],   L2E, -b0));
            const float p01 = exp2f(fmaf(sc[2*j][1],   L2E, -b0));
            const float p02 = exp2f(fmaf(sc[2*j][2],   L2E, -b1));
            const float p03 = exp2f(fmaf(sc[2*j][3],   L2E, -b1));
            const float p10 = exp2f(fmaf(sc[2*j+1][0], L2E, -b0));
            const float p11 = exp2f(fmaf(sc[2*j+1][1], L2E, -b0));
            const float p12 = exp2f(fmaf(sc[2*j+1][2], L2E, -b1));
            const float p13 = exp2f(fmaf(sc[2*j+1][3], L2E, -b1));
            l0 += p00 + p01 + p10 + p11;
            l1 += p02 + p03 + p12 + p13;
            pk[j].x = pack_h2(p00, p01);
            pk[j].y = pack_h2(p02, p03);
            pk[j].z = pack_h2(p10, p11);
            pk[j].w = pack_h2(p12, p13);
        }

        // O += P.V : 8 k16 key-tiles x 8 d-tiles
#pragma unroll
        for (int j = 0; j < 8; j++) {
#pragma unroll
            for (int dt = 0; dt < 8; dt++) {
                const uint2 b = *(const uint2*)(Vsm + (j * 8 + dt) * 64 + lane * 2);
                mma_f16(o[dt], pk[j], b.x, b.y);
            }
        }
    }

    l0 += __shfl_xor_sync(0xFFFFFFFFu, l0, 1);
    l0 += __shfl_xor_sync(0xFFFFFFFFu, l0, 2);
    l1 += __shfl_xor_sync(0xFFFFFFFFu, l1, 1);
    l1 += __shfl_xor_sync(0xFFFFFFFFu, l1, 2);
    const float inv0 = 1.f / l0, inv1 = 1.f / l1;

    // A-frag fp16 store into CATF (width 1088)
    const int b_ = bh >> 4, h = bh & 15;
    const int r0 = b_ * 1024 + qb * 128 + w * 16 + g;   // bit3 of r0%16 == 0
#pragma unroll
    for (int dt = 0; dt < 8; dt++) {
        const int cc = h * 64 + dt * 8 + tig * 2;
        uint2 wv;
        wv.x = pack_h2(o[dt][0] * inv0, o[dt][1] * inv0);
        wv.y = pack_h2(o[dt][2] * inv1, o[dt][3] * inv1);
        *(uint2*)(OUT + afrag16(r0, cc, CATD)) = wv;
    }
}

// ---------------------------------------------------------------------------
// launch
// ---------------------------------------------------------------------------
extern "C" void kernel_launch(void* const* d_in, const int* in_sizes, int n_in,
                              void* d_out, int out_size)
{
    const float* x    = (const float*)d_in[0];
    const float* Wq   = (const float*)d_in[1];
    const float* bq   = (const float*)d_in[2];
    const float* Wk   = (const float*)d_in[3];
    const float* bk   = (const float*)d_in[4];
    const float* Wv   = (const float*)d_in[5];
    const float* bv   = (const float*)d_in[6];
    const float* Win  = (const float*)d_in[7];
    const float* bin_ = (const float*)d_in[8];
    const float* W1   = (const float*)d_in[9];
    const float* b1   = (const float*)d_in[10];
    const float* W2   = (const float*)d_in[11];
    const float* b2   = (const float*)d_in[12];
    float* out = (float*)d_out;

    uint32_t *xf, *catf, *h1f, *wp, *qf, *kf, *vf;
    cudaGetSymbolAddress((void**)&xf,   g_XF);
    cudaGetSymbolAddress((void**)&catf, g_CATF);
    cudaGetSymbolAddress((void**)&h1f,  g_H1F);
    cudaGetSymbolAddress((void**)&wp,   g_WP);
    cudaGetSymbolAddress((void**)&qf,   g_QF);
    cudaGetSymbolAddress((void**)&kf,   g_KF);
    cudaGetSymbolAddress((void**)&vf,   g_VF);

    cudaFuncSetAttribute(mma_gemm, cudaFuncAttributeMaxDynamicSharedMemorySize,
                         GEMM_SMEM);
    cudaFuncSetAttribute(attn_mma, cudaFuncAttributeMaxDynamicSharedMemorySize,
                         ATT_SMEM);

    // ---- input/weight permutation (fp16 fragment-major) ----
    permute_x<<<(MTOT * DIM / 4) / 256, 256>>>(x, xf, DIM);
    permute_w<<<(512  * 256) / 256, 256>>>(Wq,  wp + WP_Q,  1024, 1024, 1024);
    permute_w<<<(512  * 256) / 256, 256>>>(Wk,  wp + WP_K,  1024, 1024, 1024);
    permute_w<<<(512  * 256) / 256, 256>>>(Wv,  wp + WP_V,  1024, 1024, 1024);
    permute_w<<<(512  * 32)  / 256, 256>>>(Win, wp + WP_IN, 1024, 64,   128);
    permute_w<<<(544  * 512) / 256, 256>>>(W1,  wp + WP_1,  1088, 2048, 2048);
    permute_w<<<(1024 * 256) / 256, 256>>>(W2,  wp + WP_2,  2048, 1024, 1024);

    const float scaling = 0.125f;   // HEAD_DIM^-0.5
    dim3 blk(256);

    // Q/K/V projections -> fragment-major fp16 scratch (Q pre-scaled)
    dim3 g_qkv(DIM / BN, MTOT / BM);          // (8, 64)
    mma_gemm<<<g_qkv, blk, GEMM_SMEM>>>(xf, wp + WP_Q, bq, qf, DIM, DIM, 0, 0, scaling, 0, 2);
    mma_gemm<<<g_qkv, blk, GEMM_SMEM>>>(xf, wp + WP_K, bk, kf, DIM, DIM, 0, 0, 1.0f, 0, 3);
    mma_gemm<<<g_qkv, blk, GEMM_SMEM>>>(xf, wp + WP_V, bv, vf, DIM, DIM, 0, 0, 1.0f, 0, 4);

    // in_ projection -> CATF columns [1024, 1088) (A-frag store)
    dim3 g_in(1, MTOT / BM);                  // (1, 64)
    mma_gemm<<<g_in, blk, GEMM_SMEM>>>(xf, wp + WP_IN, bin_, catf, HDIM, DIM, CATD, DIM, 1.0f, 0, 1);

    // flash attention (fp16 tensor cores) -> CATF columns [0, 1024)
    dim3 g_att(8, BSZ * NHEAD);               // (8, 128)
    attn_mma<<<g_att, blk, ATT_SMEM>>>(qf, kf, vf, catf);

    // FFN1: CATF @ W1 -> H1F (A-frag store, relu)
    dim3 g_f1(FFD / BN, MTOT / BM);           // (16, 64)
    mma_gemm<<<g_f1, blk, GEMM_SMEM>>>(catf, wp + WP_1, b1, h1f, FFD, CATD, FFD, 0, 1.0f, 1, 1);

    // FFN2: H1F @ W2 -> out (standard float)
    dim3 g_f2(DIM / BN, MTOT / BM);           // (8, 64)
    mma_gemm<<<g_f2, blk, GEMM_SMEM>>>(h1f, wp + WP_2, b2, out, DIM, FFD, DIM, 0, 1.0f, 0, 0);
}